// round 16
// baseline (speedup 1.0000x reference)
#include <cuda_runtime.h>
#include <cuda_bf16.h>

#define NB 4
#define NT 2048
#define ND 1024
#define NH 16
#define HD 64

#define MT 64            // q rows per CTA
#define KT 64            // k rows per tile
#define NTILES (NT / KT)
#define KD 72            // smem row stride (bf16): 144B, conflict-free

#define OUT_ELEMS (NB * NT * ND)
#define TOTE (NB * NT * ND)

// ---- smem layout (bytes): 3-stage pipeline, 111.4KB/CTA -> 2 CTAs/SM ----
#define BUFB   (KT * KD * 2)       // 9216 per buffer
#define STAGEB (4 * BUFB)          // Kh,Kl,Vh,Vl = 36864
#define NSTAGE 3
#define SM_KH(s) ((s) * STAGEB)
#define SM_KL(s) ((s) * STAGEB + BUFB)
#define SM_VH(s) ((s) * STAGEB + 2 * BUFB)
#define SM_VL(s) ((s) * STAGEB + 3 * BUFB)
#define SM_STAT  (NSTAGE * STAGEB)   // 64 rows x 2 khalf floats = 512B
#define SM_RINV  (SM_STAT + 512)     // 64 floats
#define SM_TOTAL (SM_RINV + 256)     // 111360; x2 CTAs = 222720 <= 228KB
#define OPW 68                       // O-partial scratch row stride (floats), aliases stage 0

__device__ __nv_bfloat16 g_qh[TOTE], g_ql[TOTE];
__device__ __nv_bfloat16 g_kh[TOTE], g_kl[TOTE];
__device__ __nv_bfloat16 g_vh[TOTE], g_vl[TOTE];

static __device__ __forceinline__ void split2(float a, float b, unsigned& h, unsigned& l)
{
    __nv_bfloat16 ha = __float2bfloat16(a);
    __nv_bfloat16 hb = __float2bfloat16(b);
    float ra = a - __bfloat162float(ha);
    float rb = b - __bfloat162float(hb);
    __nv_bfloat16 la = __float2bfloat16(ra);
    __nv_bfloat16 lb = __float2bfloat16(rb);
    h = (unsigned)__bfloat16_as_ushort(ha) | ((unsigned)__bfloat16_as_ushort(hb) << 16);
    l = (unsigned)__bfloat16_as_ushort(la) | ((unsigned)__bfloat16_as_ushort(lb) << 16);
}

#define MMA4(d0,d1,d2,d3,a0,a1,a2,a3,b0,b1)                              \
    asm volatile("mma.sync.aligned.m16n8k16.row.col.f32.bf16.bf16.f32 "  \
                 "{%0,%1,%2,%3},{%4,%5,%6,%7},{%8,%9},{%0,%1,%2,%3};"    \
                 : "+f"(d0), "+f"(d1), "+f"(d2), "+f"(d3)                \
                 : "r"(a0), "r"(a1), "r"(a2), "r"(a3), "r"(b0), "r"(b1))

#define LDSM4(r0,r1,r2,r3,addr)                                           \
    asm volatile("ldmatrix.sync.aligned.m8n8.x4.shared.b16 "              \
                 "{%0,%1,%2,%3}, [%4];"                                   \
                 : "=r"(r0), "=r"(r1), "=r"(r2), "=r"(r3) : "r"(addr))

#define LDSM4T(r0,r1,r2,r3,addr)                                          \
    asm volatile("ldmatrix.sync.aligned.m8n8.x4.trans.shared.b16 "        \
                 "{%0,%1,%2,%3}, [%4];"                                   \
                 : "=r"(r0), "=r"(r1), "=r"(r2), "=r"(r3) : "r"(addr))

static __device__ __forceinline__ void cpa16(void* s, const void* g)
{
    asm volatile("cp.async.cg.shared.global [%0], [%1], 16;"
                 :: "r"((unsigned)__cvta_generic_to_shared(s)), "l"(g));
}
#define CP_COMMIT() asm volatile("cp.async.commit_group;")
#define CP_WAIT(n)  asm volatile("cp.async.wait_group %0;" :: "n"(n))

// ---------------- pre-kernel: fp32 -> bf16 hi/lo (Q scaled by c) ----------------
__global__ void conv_kernel(const float4* __restrict__ q,
                            const float4* __restrict__ k,
                            const float4* __restrict__ v,
                            const float* __restrict__ ssp)
{
    const float ss = ssp[0];
    const float c  = 0.35355339059327373f / (1.0f + 0.01f * (1.0f - ss));
    const int n4 = TOTE / 4;
    const int stride = gridDim.x * blockDim.x;
    for (int i = blockIdx.x * blockDim.x + threadIdx.x; i < n4; i += stride) {
        unsigned h0, l0, h1, l1;
        float4 a = q[i];
        a.x *= c; a.y *= c; a.z *= c; a.w *= c;
        split2(a.x, a.y, h0, l0); split2(a.z, a.w, h1, l1);
        ((uint2*)g_qh)[i] = make_uint2(h0, h1);
        ((uint2*)g_ql)[i] = make_uint2(l0, l1);
        float4 bk = k[i];
        split2(bk.x, bk.y, h0, l0); split2(bk.z, bk.w, h1, l1);
        ((uint2*)g_kh)[i] = make_uint2(h0, h1);
        ((uint2*)g_kl)[i] = make_uint2(l0, l1);
        float4 bv = v[i];
        split2(bv.x, bv.y, h0, l0); split2(bv.z, bv.w, h1, l1);
        ((uint2*)g_vh)[i] = make_uint2(h0, h1);
        ((uint2*)g_vl)[i] = make_uint2(l0, l1);
    }
}

// ------- main kernel: one-pass attention, MT=64, KT=64, 3-stage, 2 CTAs/SM -------
extern __shared__ char smembuf[];

__global__ __launch_bounds__(256, 2)
void adaptive_span_attn_os(float* __restrict__ out, float* __restrict__ wts)
{
    const int qt = blockIdx.x, h = blockIdx.y, b = blockIdx.z;
    const int tid = threadIdx.x, lane = tid & 31, w = tid >> 5;
    const int r = lane >> 2, tg = lane & 3;
    const int qsub = w >> 1;          // 0..3: 16 q-rows each
    const int khalf = w & 1;          // 0..1: 32 k-cols each per tile

    const size_t headoff = (size_t)b * NT * ND + (size_t)h * HD;

    // staging map: per buffer, rows (tid>>3)+32i (i<2), 16B granule (tid&7)*8
    const int srow = tid >> 3;
    const int sc8  = (tid & 7) * 8;

    // ---- prime: K+V tile 0 -> stage 0, tile 1 -> stage 1 (two commit groups) ----
    #pragma unroll
    for (int i = 0; i < 2; i++) {
        int row = srow + i * 32;
        size_t g = headoff + (size_t)row * ND + sc8;
        int so = (row * KD + sc8) * 2;
        cpa16(smembuf + SM_KH(0) + so, g_kh + g);
        cpa16(smembuf + SM_KL(0) + so, g_kl + g);
        cpa16(smembuf + SM_VH(0) + so, g_vh + g);
        cpa16(smembuf + SM_VL(0) + so, g_vl + g);
    }
    CP_COMMIT();
    #pragma unroll
    for (int i = 0; i < 2; i++) {
        int row = srow + i * 32;
        size_t g = headoff + (size_t)(KT + row) * ND + sc8;
        int so = (row * KD + sc8) * 2;
        cpa16(smembuf + SM_KH(1) + so, g_kh + g);
        cpa16(smembuf + SM_KL(1) + so, g_kl + g);
        cpa16(smembuf + SM_VH(1) + so, g_vh + g);
        cpa16(smembuf + SM_VL(1) + so, g_vl + g);
    }
    CP_COMMIT();

    // ---- stage Q (64 x 64) hi/lo into stage-2 K buffers ----
    // Stage 2 is first written by the prefetch of tile 2 (issued inside iteration
    // t=0, AFTER the t=0 barrier). All Q-fragment reads happen before that barrier.
    #pragma unroll
    for (int j = 0; j < 2; j++) {
        int g8 = tid * 2 + j;                 // 512 granules of 8 bf16
        int row = g8 >> 3, c = (g8 & 7) * 8;
        size_t g = headoff + (size_t)(qt * MT + row) * ND + c;
        *(uint4*)(smembuf + SM_KH(2) + (row * KD + c) * 2) = *(const uint4*)(g_qh + g);
        *(uint4*)(smembuf + SM_KL(2) + (row * KD + c) * 2) = *(const uint4*)(g_ql + g);
    }
    __syncthreads();

    // ---- Q fragments for this warp's 16 q-rows ----
    unsigned ah[4][4], al[4][4];
    {
        const __nv_bfloat16* Qh = (const __nv_bfloat16*)(smembuf + SM_KH(2));
        const __nv_bfloat16* Ql = (const __nv_bfloat16*)(smembuf + SM_KL(2));
        const int row0 = qsub * 16 + r;
        #pragma unroll
        for (int ks = 0; ks < 4; ks++) {
            int c0 = ks * 16 + tg * 2;
            ah[ks][0] = *(const unsigned*)(Qh + row0 * KD + c0);
            ah[ks][1] = *(const unsigned*)(Qh + (row0 + 8) * KD + c0);
            ah[ks][2] = *(const unsigned*)(Qh + row0 * KD + c0 + 8);
            ah[ks][3] = *(const unsigned*)(Qh + (row0 + 8) * KD + c0 + 8);
            al[ks][0] = *(const unsigned*)(Ql + row0 * KD + c0);
            al[ks][1] = *(const unsigned*)(Ql + (row0 + 8) * KD + c0);
            al[ks][2] = *(const unsigned*)(Ql + row0 * KD + c0 + 8);
            al[ks][3] = *(const unsigned*)(Ql + (row0 + 8) * KD + c0 + 8);
        }
    }

    float o[8][4];
    #pragma unroll
    for (int nf = 0; nf < 8; nf++) { o[nf][0] = 0.f; o[nf][1] = 0.f; o[nf][2] = 0.f; o[nf][3] = 0.f; }
    float lsum0 = 0.f, lsum1 = 0.f;

    // ldmatrix lane maps (verified): non-trans vs trans have opposite bit3/bit4 roles
    const int k_lmr = (lane & 7) + ((lane >> 4) & 1) * 8;   // bit4 -> row
    const int k_lmd = ((lane >> 3) & 1) * 8;                // bit3 -> col
    const int v_lmr = (lane & 7) + ((lane >> 3) & 1) * 8;   // bit3 -> row
    const int v_lmd = ((lane >> 4) & 1) * 8;                // bit4 -> col

    float* wbase = wts + ((size_t)((b * NH + h) * NT) + (size_t)(qt * MT)) * NT;

    int st = 0;                       // stage of tile t (t % 3)
    #pragma unroll 1
    for (int t = 0; t < NTILES; t++) {
        // group algebra: committed groups so far = tiles 0..t+1; waiting to <=1
        // outstanding leaves only tile t+1 in flight => tile t's data is visible.
        if (t + 1 < NTILES) { CP_WAIT(1); } else { CP_WAIT(0); }
        __syncthreads();   // tile-t visible to all; all warps done computing tile t-1

        // prefetch tile t+2 into stage (t+2)%3 == stage of tile t-1, just vacated
        if (t + 2 < NTILES) {
            const int sn = (st + 2 >= NSTAGE) ? st + 2 - NSTAGE : st + 2;
            #pragma unroll
            for (int i = 0; i < 2; i++) {
                int row = srow + i * 32;
                size_t g = headoff + (size_t)((t + 2) * KT + row) * ND + sc8;
                int so = (row * KD + sc8) * 2;
                cpa16(smembuf + SM_KH(sn) + so, g_kh + g);
                cpa16(smembuf + SM_KL(sn) + so, g_kl + g);
                cpa16(smembuf + SM_VH(sn) + so, g_vh + g);
                cpa16(smembuf + SM_VL(sn) + so, g_vl + g);
            }
            CP_COMMIT();
        }

        const __nv_bfloat16* Kh = (const __nv_bfloat16*)(smembuf + SM_KH(st));
        const __nv_bfloat16* Kl = (const __nv_bfloat16*)(smembuf + SM_KL(st));
        const __nv_bfloat16* Vh = (const __nv_bfloat16*)(smembuf + SM_VH(st));
        const __nv_bfloat16* Vl = (const __nv_bfloat16*)(smembuf + SM_VL(st));

        // ---- S tile: 16q x 32k (this warp's half of KT=64), K frags via ldmatrix.x4 ----
        float s[4][4];
        #pragma unroll
        for (int p = 0; p < 2; p++) {              // 16-col k blocks
            float* sa = s[2 * p];
            float* sb = s[2 * p + 1];
            sa[0] = 0.f; sa[1] = 0.f; sa[2] = 0.f; sa[3] = 0.f;
            sb[0] = 0.f; sb[1] = 0.f; sb[2] = 0.f; sb[3] = 0.f;
            const int krow = khalf * 32 + p * 16 + k_lmr;
            #pragma unroll
            for (int ks = 0; ks < 4; ks++) {
                unsigned h0, h1, h2, h3, l0, l1, l2, l3;
                unsigned hadd = (unsigned)__cvta_generic_to_shared(Kh + krow * KD + ks * 16 + k_lmd);
                unsigned ladd = (unsigned)__cvta_generic_to_shared(Kl + krow * KD + ks * 16 + k_lmd);
                LDSM4(h0, h1, h2, h3, hadd);
                LDSM4(l0, l1, l2, l3, ladd);
                MMA4(sa[0], sa[1], sa[2], sa[3], ah[ks][0], ah[ks][1], ah[ks][2], ah[ks][3], h0, h1);
                MMA4(sb[0], sb[1], sb[2], sb[3], ah[ks][0], ah[ks][1], ah[ks][2], ah[ks][3], h2, h3);
                MMA4(sa[0], sa[1], sa[2], sa[3], ah[ks][0], ah[ks][1], ah[ks][2], ah[ks][3], l0, l1);
                MMA4(sb[0], sb[1], sb[2], sb[3], ah[ks][0], ah[ks][1], ah[ks][2], ah[ks][3], l2, l3);
                MMA4(sa[0], sa[1], sa[2], sa[3], al[ks][0], al[ks][1], al[ks][2], al[ks][3], h0, h1);
                MMA4(sb[0], sb[1], sb[2], sb[3], al[ks][0], al[ks][1], al[ks][2], al[ks][3], h2, h3);
            }
        }

        // ---- exp (no-max; scores bounded, shift 10) + sums + W-hat store ----
        #pragma unroll
        for (int nf = 0; nf < 4; nf++) {
            float e0 = __expf(s[nf][0] - 10.0f);
            float e1 = __expf(s[nf][1] - 10.0f);
            float e2 = __expf(s[nf][2] - 10.0f);
            float e3 = __expf(s[nf][3] - 10.0f);
            s[nf][0] = e0; s[nf][1] = e1; s[nf][2] = e2; s[nf][3] = e3;
            lsum0 += e0 + e1; lsum1 += e2 + e3;
        }
        {
            float* wr0 = wbase + (size_t)(qsub * 16 + r) * NT + t * KT + khalf * 32;
            float* wr8 = wr0 + (size_t)8 * NT;
            #pragma unroll
            for (int nf = 0; nf < 4; nf++) {
                int c = nf * 8 + tg * 2;
                *(float2*)(wr0 + c) = make_float2(s[nf][0], s[nf][1]);
                *(float2*)(wr8 + c) = make_float2(s[nf][2], s[nf][3]);
            }
        }

        // ---- O += What * V (trans ldmatrix with the trans lane map) ----
        #pragma unroll
        for (int ks2 = 0; ks2 < 2; ks2++) {
            unsigned wh[4], wl[4];
            split2(s[2 * ks2][0],     s[2 * ks2][1],     wh[0], wl[0]);
            split2(s[2 * ks2][2],     s[2 * ks2][3],     wh[1], wl[1]);
            split2(s[2 * ks2 + 1][0], s[2 * ks2 + 1][1], wh[2], wl[2]);
            split2(s[2 * ks2 + 1][2], s[2 * ks2 + 1][3], wh[3], wl[3]);
            const int krow = khalf * 32 + ks2 * 16 + v_lmr;
            #pragma unroll
            for (int nfp = 0; nfp < 4; nfp++) {
                int dcol = nfp * 16 + v_lmd;
                unsigned bh0, bh1, bh2, bh3, bl0, bl1, bl2, bl3;
                unsigned haddr = (unsigned)__cvta_generic_to_shared(Vh + krow * KD + dcol);
                unsigned laddr = (unsigned)__cvta_generic_to_shared(Vl + krow * KD + dcol);
                LDSM4T(bh0, bh1, bh2, bh3, haddr);
                LDSM4T(bl0, bl1, bl2, bl3, laddr);
                float* oa = o[nfp * 2];
                float* ob = o[nfp * 2 + 1];
                MMA4(oa[0], oa[1], oa[2], oa[3], wh[0], wh[1], wh[2], wh[3], bh0, bh1);
                MMA4(ob[0], ob[1], ob[2], ob[3], wh[0], wh[1], wh[2], wh[3], bh2, bh3);
                MMA4(oa[0], oa[1], oa[2], oa[3], wh[0], wh[1], wh[2], wh[3], bl0, bl1);
                MMA4(ob[0], ob[1], ob[2], ob[3], wh[0], wh[1], wh[2], wh[3], bl2, bl3);
                MMA4(oa[0], oa[1], oa[2], oa[3], wl[0], wl[1], wl[2], wl[3], bh0, bh1);
                MMA4(ob[0], ob[1], ob[2], ob[3], wl[0], wl[1], wl[2], wl[3], bh2, bh3);
            }
        }

        st = (st + 1 == NSTAGE) ? 0 : st + 1;
    }

    // ================= sums -> 1/sum table =================
    float* stat = (float*)(smembuf + SM_STAT);
    float* rinv = (float*)(smembuf + SM_RINV);

    lsum0 += __shfl_xor_sync(0xffffffffu, lsum0, 1);
    lsum0 += __shfl_xor_sync(0xffffffffu, lsum0, 2);
    lsum1 += __shfl_xor_sync(0xffffffffu, lsum1, 1);
    lsum1 += __shfl_xor_sync(0xffffffffu, lsum1, 2);
    if (tg == 0) {
        stat[(qsub * 16 + r) * 2 + khalf]     = lsum0;
        stat[(qsub * 16 + r + 8) * 2 + khalf] = lsum1;
    }
    __syncthreads();   // also proves all compute done before OP aliasing below
    if (tid < 64) rinv[tid] = 1.0f / (stat[tid * 2] + stat[tid * 2 + 1]);

    // ---- O cross-khalf reduce (scratch aliases stage 0; 4 slots x 16 x OPW) ----
    float* OP = (float*)smembuf;
    if (khalf == 1) {
        float* opw = OP + qsub * (16 * OPW);
        #pragma unroll
        for (int nf = 0; nf < 8; nf++) {
            int c = nf * 8 + tg * 2;
            *(float2*)(opw + r * OPW + c)       = make_float2(o[nf][0], o[nf][1]);
            *(float2*)(opw + (r + 8) * OPW + c) = make_float2(o[nf][2], o[nf][3]);
        }
    }
    __syncthreads();
    if (khalf == 0) {
        const float inv0 = rinv[qsub * 16 + r];
        const float inv1 = rinv[qsub * 16 + r + 8];
        const float* opw = OP + qsub * (16 * OPW);
        float* op0 = out + ((size_t)(b * NT + qt * MT + qsub * 16 + r)) * ND + h * HD;
        float* op8 = op0 + (size_t)8 * ND;
        #pragma unroll
        for (int nf = 0; nf < 8; nf++) {
            int c = nf * 8 + tg * 2;
            float2 p0 = *(const float2*)(opw + r * OPW + c);
            float2 p8 = *(const float2*)(opw + (r + 8) * OPW + c);
            *(float2*)(op0 + c) = make_float2((o[nf][0] + p0.x) * inv0, (o[nf][1] + p0.y) * inv0);
            *(float2*)(op8 + c) = make_float2((o[nf][2] + p8.x) * inv1, (o[nf][3] + p8.y) * inv1);
        }
    }
    __syncthreads();

    // ================= W renorm: re-read own 512KB (L2-resident), scale, stream out =====
    for (int rr = 0; rr < MT; rr++) {
        const float inv = rinv[rr];
        float4* wr = (float4*)(wbase + (size_t)rr * NT);
        #pragma unroll
        for (int j = 0; j < 2; j++) {
            float4 vv = wr[tid + j * 256];
            vv.x *= inv; vv.y *= inv; vv.z *= inv; vv.w *= inv;
            __stcs(wr + tid + j * 256, vv);
        }
    }
}

extern "C" void kernel_launch(void* const* d_in, const int* in_sizes, int n_in,
                              void* d_out, int out_size)
{
    const float* q  = (const float*)d_in[0];
    const float* k  = (const float*)d_in[1];
    const float* v  = (const float*)d_in[2];
    const float* ss = (const float*)d_in[5];

    float* out = (float*)d_out;
    float* wts = out + OUT_ELEMS;

    static bool attr_set = false;
    if (!attr_set) {
        cudaFuncSetAttribute(adaptive_span_attn_os,
                             cudaFuncAttributeMaxDynamicSharedMemorySize, SM_TOTAL);
        attr_set = true;
    }

    conv_kernel<<<1536, 256>>>((const float4*)q, (const float4*)k, (const float4*)v, ss);

    dim3 grid(NT / MT, NH, NB);
    adaptive_span_attn_os<<<grid, 256, SM_TOTAL>>>(out, wts);
}

// round 17
// speedup vs baseline: 1.1283x; 1.1283x over previous
#include <cuda_runtime.h>
#include <cuda_bf16.h>

#define NB 4
#define NT 2048
#define ND 1024
#define NH 16
#define HD 64

#define MT 64            // q rows per CTA
#define KT 32            // k rows per tile (small: 4 CTAs/SM)
#define NTILES (NT / KT)
#define KD 72            // smem row stride (bf16): 144B, conflict-free

#define OUT_ELEMS (NB * NT * ND)
#define TOTE (NB * NT * ND)

// ---- smem layout (bytes): 2-stage pipeline, 37KB/CTA -> 4 CTAs/SM (148KB) ----
#define BUFB   (KT * KD * 2)       // 4608 per buffer
#define STAGEB (4 * BUFB)          // Kh,Kl,Vh,Vl = 18432
#define SM_KH(s) ((s) * STAGEB)
#define SM_KL(s) ((s) * STAGEB + BUFB)
#define SM_VH(s) ((s) * STAGEB + 2 * BUFB)
#define SM_VL(s) ((s) * STAGEB + 3 * BUFB)
#define SM_RINV  (2 * STAGEB)      // 64 floats
#define SM_TOTAL (SM_RINV + 256)   // 37120

__device__ __nv_bfloat16 g_qh[TOTE], g_ql[TOTE];
__device__ __nv_bfloat16 g_kh[TOTE], g_kl[TOTE];
__device__ __nv_bfloat16 g_vh[TOTE], g_vl[TOTE];

static __device__ __forceinline__ void split2(float a, float b, unsigned& h, unsigned& l)
{
    __nv_bfloat16 ha = __float2bfloat16(a);
    __nv_bfloat16 hb = __float2bfloat16(b);
    float ra = a - __bfloat162float(ha);
    float rb = b - __bfloat162float(hb);
    __nv_bfloat16 la = __float2bfloat16(ra);
    __nv_bfloat16 lb = __float2bfloat16(rb);
    h = (unsigned)__bfloat16_as_ushort(ha) | ((unsigned)__bfloat16_as_ushort(hb) << 16);
    l = (unsigned)__bfloat16_as_ushort(la) | ((unsigned)__bfloat16_as_ushort(lb) << 16);
}

#define MMA4(d0,d1,d2,d3,a0,a1,a2,a3,b0,b1)                              \
    asm volatile("mma.sync.aligned.m16n8k16.row.col.f32.bf16.bf16.f32 "  \
                 "{%0,%1,%2,%3},{%4,%5,%6,%7},{%8,%9},{%0,%1,%2,%3};"    \
                 : "+f"(d0), "+f"(d1), "+f"(d2), "+f"(d3)                \
                 : "r"(a0), "r"(a1), "r"(a2), "r"(a3), "r"(b0), "r"(b1))

#define LDSM4(r0,r1,r2,r3,addr)                                           \
    asm volatile("ldmatrix.sync.aligned.m8n8.x4.shared.b16 "              \
                 "{%0,%1,%2,%3}, [%4];"                                   \
                 : "=r"(r0), "=r"(r1), "=r"(r2), "=r"(r3) : "r"(addr))

#define LDSM4T(r0,r1,r2,r3,addr)                                          \
    asm volatile("ldmatrix.sync.aligned.m8n8.x4.trans.shared.b16 "        \
                 "{%0,%1,%2,%3}, [%4];"                                   \
                 : "=r"(r0), "=r"(r1), "=r"(r2), "=r"(r3) : "r"(addr))

static __device__ __forceinline__ void cpa16(void* s, const void* g)
{
    asm volatile("cp.async.cg.shared.global [%0], [%1], 16;"
                 :: "r"((unsigned)__cvta_generic_to_shared(s)), "l"(g));
}
#define CP_COMMIT() asm volatile("cp.async.commit_group;")
#define CP_WAIT(n)  asm volatile("cp.async.wait_group %0;" :: "n"(n))

// ---------------- pre-kernel: fp32 -> bf16 hi/lo (Q scaled by c) ----------------
__global__ void conv_kernel(const float4* __restrict__ q,
                            const float4* __restrict__ k,
                            const float4* __restrict__ v,
                            const float* __restrict__ ssp)
{
    const float ss = ssp[0];
    const float c  = 0.35355339059327373f / (1.0f + 0.01f * (1.0f - ss));
    const int n4 = TOTE / 4;
    const int stride = gridDim.x * blockDim.x;
    for (int i = blockIdx.x * blockDim.x + threadIdx.x; i < n4; i += stride) {
        unsigned h0, l0, h1, l1;
        float4 a = q[i];
        a.x *= c; a.y *= c; a.z *= c; a.w *= c;
        split2(a.x, a.y, h0, l0); split2(a.z, a.w, h1, l1);
        ((uint2*)g_qh)[i] = make_uint2(h0, h1);
        ((uint2*)g_ql)[i] = make_uint2(l0, l1);
        float4 bk = k[i];
        split2(bk.x, bk.y, h0, l0); split2(bk.z, bk.w, h1, l1);
        ((uint2*)g_kh)[i] = make_uint2(h0, h1);
        ((uint2*)g_kl)[i] = make_uint2(l0, l1);
        float4 bv = v[i];
        split2(bv.x, bv.y, h0, l0); split2(bv.z, bv.w, h1, l1);
        ((uint2*)g_vh)[i] = make_uint2(h0, h1);
        ((uint2*)g_vl)[i] = make_uint2(l0, l1);
    }
}

// ------- main kernel: one-pass attention, MT=64, KT=32, 128 thr, 4 CTAs/SM -------
// 4 warps = 4 q-subtiles; each warp covers the FULL k-width of each tile.
extern __shared__ char smembuf[];

__global__ __launch_bounds__(128, 4)
void adaptive_span_attn_os(float* __restrict__ out, float* __restrict__ wts)
{
    const int qt = blockIdx.x, h = blockIdx.y, b = blockIdx.z;
    const int tid = threadIdx.x, lane = tid & 31, w = tid >> 5;
    const int r = lane >> 2, tg = lane & 3;
    const int qsub = w;               // 0..3: 16 q-rows each

    const size_t headoff = (size_t)b * NT * ND + (size_t)h * HD;

    // ---- prime: K+V tile 0 into stage 0 (ONE commit group) ----
    // per buffer: 32 rows x 8 granules(16B) = 256; 128 threads x 2
    #pragma unroll
    for (int i = 0; i < 2; i++) {
        int g8 = tid + i * 128;
        int row = g8 >> 3, sc8 = (g8 & 7) * 8;
        size_t g = headoff + (size_t)row * ND + sc8;
        int so = (row * KD + sc8) * 2;
        cpa16(smembuf + SM_KH(0) + so, g_kh + g);
        cpa16(smembuf + SM_KL(0) + so, g_kl + g);
        cpa16(smembuf + SM_VH(0) + so, g_vh + g);
        cpa16(smembuf + SM_VL(0) + so, g_vl + g);
    }
    CP_COMMIT();

    // ---- stage Q (64 x 64) hi/lo into stage-1 buffers: rows 0-31 -> KH(1)/KL(1),
    //      rows 32-63 -> VH(1)/VL(1). First overwritten by the tile-1 prefetch in
    //      iteration t=0, AFTER the t=0 barrier; all Q-frag reads precede it. ----
    #pragma unroll
    for (int j = 0; j < 4; j++) {
        int g8 = tid + j * 128;               // 512 granules of 8 bf16
        int row = g8 >> 3, c = (g8 & 7) * 8;
        size_t g = headoff + (size_t)(qt * MT + row) * ND + c;
        int lrow = row & 31;
        int soH = ((row < 32) ? SM_KH(1) : SM_VH(1)) + (lrow * KD + c) * 2;
        int soL = ((row < 32) ? SM_KL(1) : SM_VL(1)) + (lrow * KD + c) * 2;
        *(uint4*)(smembuf + soH) = *(const uint4*)(g_qh + g);
        *(uint4*)(smembuf + soL) = *(const uint4*)(g_ql + g);
    }
    __syncthreads();

    // ---- Q fragments for this warp's 16 q-rows ----
    unsigned ah[4][4], al[4][4];
    {
        const __nv_bfloat16* Qh = (const __nv_bfloat16*)(smembuf + ((qsub < 2) ? SM_KH(1) : SM_VH(1)));
        const __nv_bfloat16* Ql = (const __nv_bfloat16*)(smembuf + ((qsub < 2) ? SM_KL(1) : SM_VL(1)));
        const int row0 = (qsub & 1) * 16 + r;
        #pragma unroll
        for (int ks = 0; ks < 4; ks++) {
            int c0 = ks * 16 + tg * 2;
            ah[ks][0] = *(const unsigned*)(Qh + row0 * KD + c0);
            ah[ks][1] = *(const unsigned*)(Qh + (row0 + 8) * KD + c0);
            ah[ks][2] = *(const unsigned*)(Qh + row0 * KD + c0 + 8);
            ah[ks][3] = *(const unsigned*)(Qh + (row0 + 8) * KD + c0 + 8);
            al[ks][0] = *(const unsigned*)(Ql + row0 * KD + c0);
            al[ks][1] = *(const unsigned*)(Ql + (row0 + 8) * KD + c0);
            al[ks][2] = *(const unsigned*)(Ql + row0 * KD + c0 + 8);
            al[ks][3] = *(const unsigned*)(Ql + (row0 + 8) * KD + c0 + 8);
        }
    }

    float o[8][4];
    #pragma unroll
    for (int nf = 0; nf < 8; nf++) { o[nf][0] = 0.f; o[nf][1] = 0.f; o[nf][2] = 0.f; o[nf][3] = 0.f; }
    float lsum0 = 0.f, lsum1 = 0.f;

    // ldmatrix lane maps (verified): non-trans vs trans have opposite bit3/bit4 roles
    const int k_lmr = (lane & 7) + ((lane >> 4) & 1) * 8;   // bit4 -> row
    const int k_lmd = ((lane >> 3) & 1) * 8;                // bit3 -> col
    const int v_lmr = (lane & 7) + ((lane >> 3) & 1) * 8;   // bit3 -> row
    const int v_lmd = ((lane >> 4) & 1) * 8;                // bit4 -> col

    float* wbase = wts + ((size_t)((b * NH + h) * NT) + (size_t)(qt * MT)) * NT;

    #pragma unroll 1
    for (int t = 0; t < NTILES; t++) {
        const int st = t & 1;
        CP_WAIT(0);        // only outstanding group is tile t's
        __syncthreads();   // tile-t visible to all 4 warps; tile t-1 compute done

        // prefetch tile t+1 into the buffer just vacated
        if (t + 1 < NTILES) {
            const int sn = (t + 1) & 1;
            #pragma unroll
            for (int i = 0; i < 2; i++) {
                int g8 = tid + i * 128;
                int row = g8 >> 3, sc8 = (g8 & 7) * 8;
                size_t g = headoff + (size_t)((t + 1) * KT + row) * ND + sc8;
                int so = (row * KD + sc8) * 2;
                cpa16(smembuf + SM_KH(sn) + so, g_kh + g);
                cpa16(smembuf + SM_KL(sn) + so, g_kl + g);
                cpa16(smembuf + SM_VH(sn) + so, g_vh + g);
                cpa16(smembuf + SM_VL(sn) + so, g_vl + g);
            }
            CP_COMMIT();
        }

        const __nv_bfloat16* Kh = (const __nv_bfloat16*)(smembuf + SM_KH(st));
        const __nv_bfloat16* Kl = (const __nv_bfloat16*)(smembuf + SM_KL(st));
        const __nv_bfloat16* Vh = (const __nv_bfloat16*)(smembuf + SM_VH(st));
        const __nv_bfloat16* Vl = (const __nv_bfloat16*)(smembuf + SM_VL(st));

        // ---- S tile: 16q x 32k (full tile width), K frags via ldmatrix.x4 ----
        float s[4][4];
        #pragma unroll
        for (int p = 0; p < 2; p++) {              // 16-row k blocks
            float* sa = s[2 * p];
            float* sb = s[2 * p + 1];
            sa[0] = 0.f; sa[1] = 0.f; sa[2] = 0.f; sa[3] = 0.f;
            sb[0] = 0.f; sb[1] = 0.f; sb[2] = 0.f; sb[3] = 0.f;
            const int krow = p * 16 + k_lmr;
            #pragma unroll
            for (int ks = 0; ks < 4; ks++) {
                unsigned h0, h1, h2, h3, l0, l1, l2, l3;
                unsigned hadd = (unsigned)__cvta_generic_to_shared(Kh + krow * KD + ks * 16 + k_lmd);
                unsigned ladd = (unsigned)__cvta_generic_to_shared(Kl + krow * KD + ks * 16 + k_lmd);
                LDSM4(h0, h1, h2, h3, hadd);
                LDSM4(l0, l1, l2, l3, ladd);
                MMA4(sa[0], sa[1], sa[2], sa[3], ah[ks][0], ah[ks][1], ah[ks][2], ah[ks][3], h0, h1);
                MMA4(sb[0], sb[1], sb[2], sb[3], ah[ks][0], ah[ks][1], ah[ks][2], ah[ks][3], h2, h3);
                MMA4(sa[0], sa[1], sa[2], sa[3], ah[ks][0], ah[ks][1], ah[ks][2], ah[ks][3], l0, l1);
                MMA4(sb[0], sb[1], sb[2], sb[3], ah[ks][0], ah[ks][1], ah[ks][2], ah[ks][3], l2, l3);
                MMA4(sa[0], sa[1], sa[2], sa[3], al[ks][0], al[ks][1], al[ks][2], al[ks][3], h0, h1);
                MMA4(sb[0], sb[1], sb[2], sb[3], al[ks][0], al[ks][1], al[ks][2], al[ks][3], h2, h3);
            }
        }

        // ---- exp (no-max; scores bounded, shift 10) + sums + W-hat store ----
        #pragma unroll
        for (int nf = 0; nf < 4; nf++) {
            float e0 = __expf(s[nf][0] - 10.0f);
            float e1 = __expf(s[nf][1] - 10.0f);
            float e2 = __expf(s[nf][2] - 10.0f);
            float e3 = __expf(s[nf][3] - 10.0f);
            s[nf][0] = e0; s[nf][1] = e1; s[nf][2] = e2; s[nf][3] = e3;
            lsum0 += e0 + e1; lsum1 += e2 + e3;
        }
        {
            float* wr0 = wbase + (size_t)(qsub * 16 + r) * NT + t * KT;
            float* wr8 = wr0 + (size_t)8 * NT;
            #pragma unroll
            for (int nf = 0; nf < 4; nf++) {
                int c = nf * 8 + tg * 2;
                *(float2*)(wr0 + c) = make_float2(s[nf][0], s[nf][1]);
                *(float2*)(wr8 + c) = make_float2(s[nf][2], s[nf][3]);
            }
        }

        // ---- O += What * V (trans ldmatrix with the trans lane map) ----
        #pragma unroll
        for (int ks2 = 0; ks2 < 2; ks2++) {
            unsigned wh[4], wl[4];
            split2(s[2 * ks2][0],     s[2 * ks2][1],     wh[0], wl[0]);
            split2(s[2 * ks2][2],     s[2 * ks2][3],     wh[1], wl[1]);
            split2(s[2 * ks2 + 1][0], s[2 * ks2 + 1][1], wh[2], wl[2]);
            split2(s[2 * ks2 + 1][2], s[2 * ks2 + 1][3], wh[3], wl[3]);
            const int krow = ks2 * 16 + v_lmr;
            #pragma unroll
            for (int nfp = 0; nfp < 4; nfp++) {
                int dcol = nfp * 16 + v_lmd;
                unsigned bh0, bh1, bh2, bh3, bl0, bl1, bl2, bl3;
                unsigned haddr = (unsigned)__cvta_generic_to_shared(Vh + krow * KD + dcol);
                unsigned laddr = (unsigned)__cvta_generic_to_shared(Vl + krow * KD + dcol);
                LDSM4T(bh0, bh1, bh2, bh3, haddr);
                LDSM4T(bl0, bl1, bl2, bl3, laddr);
                float* oa = o[nfp * 2];
                float* ob = o[nfp * 2 + 1];
                MMA4(oa[0], oa[1], oa[2], oa[3], wh[0], wh[1], wh[2], wh[3], bh0, bh1);
                MMA4(ob[0], ob[1], ob[2], ob[3], wh[0], wh[1], wh[2], wh[3], bh2, bh3);
                MMA4(oa[0], oa[1], oa[2], oa[3], wh[0], wh[1], wh[2], wh[3], bl0, bl1);
                MMA4(ob[0], ob[1], ob[2], ob[3], wh[0], wh[1], wh[2], wh[3], bl2, bl3);
                MMA4(oa[0], oa[1], oa[2], oa[3], wl[0], wl[1], wl[2], wl[3], bh0, bh1);
                MMA4(ob[0], ob[1], ob[2], ob[3], wl[0], wl[1], wl[2], wl[3], bh2, bh3);
            }
        }
    }

    // ================= per-warp row sums are COMPLETE (full k coverage) =============
    lsum0 += __shfl_xor_sync(0xffffffffu, lsum0, 1);
    lsum0 += __shfl_xor_sync(0xffffffffu, lsum0, 2);
    lsum1 += __shfl_xor_sync(0xffffffffu, lsum1, 1);
    lsum1 += __shfl_xor_sync(0xffffffffu, lsum1, 2);
    const float inv0 = 1.0f / lsum0;
    const float inv1 = 1.0f / lsum1;

    float* rinv = (float*)(smembuf + SM_RINV);
    if (tg == 0) {
        rinv[qsub * 16 + r]     = inv0;
        rinv[qsub * 16 + r + 8] = inv1;
    }

    // ---- O writeout straight from registers (no cross-warp reduce needed) ----
    {
        float* op0 = out + ((size_t)(b * NT + qt * MT + qsub * 16 + r)) * ND + h * HD;
        float* op8 = op0 + (size_t)8 * ND;
        #pragma unroll
        for (int nf = 0; nf < 8; nf++) {
            int c = nf * 8 + tg * 2;
            *(float2*)(op0 + c) = make_float2(o[nf][0] * inv0, o[nf][1] * inv0);
            *(float2*)(op8 + c) = make_float2(o[nf][2] * inv1, o[nf][3] * inv1);
        }
    }
    __syncthreads();   // rinv table complete for all 64 rows

    // ================= W renorm: re-read own 512KB (L2-resident), scale, stream out =====
    for (int rr = 0; rr < MT; rr++) {
        const float inv = rinv[rr];
        float4* wr = (float4*)(wbase + (size_t)rr * NT);
        #pragma unroll
        for (int j = 0; j < 4; j++) {
            int idx = tid + j * 128;
            float4 vv = wr[idx];
            vv.x *= inv; vv.y *= inv; vv.z *= inv; vv.w *= inv;
            __stcs(wr + idx, vv);
        }
    }
}

extern "C" void kernel_launch(void* const* d_in, const int* in_sizes, int n_in,
                              void* d_out, int out_size)
{
    const float* q  = (const float*)d_in[0];
    const float* k  = (const float*)d_in[1];
    const float* v  = (const float*)d_in[2];
    const float* ss = (const float*)d_in[5];

    float* out = (float*)d_out;
    float* wts = out + OUT_ELEMS;

    static bool attr_set = false;
    if (!attr_set) {
        cudaFuncSetAttribute(adaptive_span_attn_os,
                             cudaFuncAttributeMaxDynamicSharedMemorySize, SM_TOTAL);
        attr_set = true;
    }

    conv_kernel<<<1536, 256>>>((const float4*)q, (const float4*)k, (const float4*)v, ss);

    dim3 grid(NT / MT, NH, NB);
    adaptive_span_attn_os<<<grid, 128, SM_TOTAL>>>(out, wts);
}